// round 3
// baseline (speedup 1.0000x reference)
#include <cuda_runtime.h>

#define Bb 2
#define Nn 8192
#define Ff 64
#define Oo 64
#define GRID 128
#define TPB 256
#define RPB 128          // rows per block
#define ITERS 8          // RPB / 16 row groups

// Scratch (__device__ globals; zero-initialized at module load).
__device__ float g_part_Sj[GRID];
__device__ float g_u[Bb * Ff];          // atomic accumulators (zeroed in-kernel)
__device__ float g_v[Bb * Ff];
__device__ unsigned int g_flag[GRID];   // monotone per-block barrier flags

__device__ __forceinline__ unsigned int flag_load_acq(const unsigned int* p) {
    unsigned int v;
    asm volatile("ld.acquire.gpu.global.u32 %0, [%1];" : "=r"(v) : "l"(p) : "memory");
    return v;
}
__device__ __forceinline__ void flag_store_rel(unsigned int* p, unsigned int v) {
    asm volatile("st.release.gpu.global.u32 [%0], %1;" :: "l"(p), "r"(v) : "memory");
}

// Distributed-flag grid barrier: arrive = release-store own flag (monotone),
// wait = 128 threads acquire-poll one flag each. Wrap-safe compare.
__device__ __forceinline__ void grid_barrier(unsigned int target) {
    __syncthreads();
    if (threadIdx.x == 0) flag_store_rel(&g_flag[blockIdx.x], target);
    if (threadIdx.x < GRID) {
        while ((int)(flag_load_acq(&g_flag[threadIdx.x]) - target) < 0) { }
    }
    __syncthreads();
}

__global__ void __launch_bounds__(TPB, 1) k_fused(
    const float* __restrict__ x, const float* __restrict__ adj_w,
    const float* __restrict__ adj_b, const float* __restrict__ weight,
    const float* __restrict__ bias, float* __restrict__ out)
{
    __shared__ float s_si[RPB], s_sj[RPB];
    __shared__ float s_pu[16 * Ff];
    __shared__ float s_pv[16 * Ff];
    __shared__ float s_u[Ff], s_v[Ff];
    __shared__ float sP[Oo], sQ[Oo], sB[Oo];
    __shared__ float s_W[Ff * Oo];        // 16 KB weight stage
    __shared__ float s_blkSj, s_Sj;

    const int tid  = threadIdx.x;
    const int lane = tid & 15;            // feature quad
    const int grp  = tid >> 4;            // row group
    const int bid  = blockIdx.x;
    const int bb   = bid >> 6;            // batch (64 blocks/batch)
    const int row0 = bid * RPB;

    // Per-launch epoch: all flags equal at launch entry (each launch adds 2).
    const unsigned int epoch = g_flag[bid];

    const float c = adj_b[0];
    if (tid == 0) s_blkSj = 0.0f;

    // Stage weight + bias into shared (latency overlapped with phase 1 + barrier 1).
    #pragma unroll
    for (int k = 0; k < Ff * Oo / TPB; ++k)
        s_W[k * TPB + tid] = weight[k * TPB + tid];
    if (tid < Oo) sB[tid] = bias[tid];

    // Block 0 zeroes the u/v atomic accumulators; release at barrier 1 publishes.
    if (bid == 0) { g_u[tid >> 1] = 0.0f; g_v[tid >> 1] = 0.0f; }  // 256 thr / 128 slots: benign dup
    if (bid == 1 && tid < 128) { g_u[tid] = 0.0f; }                // (redundant safety)

    // ---------------- Phase 1: si/sj + block Sj partial ----------------------
    float4 xv[ITERS];
    #pragma unroll
    for (int it = 0; it < ITERS; ++it)
        xv[it] = reinterpret_cast<const float4*>(x)[(row0 + it * 16 + grp) * 16 + lane];

    const float4 wj = reinterpret_cast<const float4*>(adj_w)[lane];
    const float4 wi = reinterpret_cast<const float4*>(adj_w)[16 + lane];

    float bsum = 0.0f;
    #pragma unroll
    for (int it = 0; it < ITERS; ++it) {
        float pj = xv[it].x * wj.x + xv[it].y * wj.y + xv[it].z * wj.z + xv[it].w * wj.w;
        float pi = xv[it].x * wi.x + xv[it].y * wi.y + xv[it].z * wi.z + xv[it].w * wi.w;
        #pragma unroll
        for (int off = 8; off; off >>= 1) {
            pj += __shfl_down_sync(0xffffffffu, pj, off, 16);
            pi += __shfl_down_sync(0xffffffffu, pi, off, 16);
        }
        if (lane == 0) {
            s_si[it * 16 + grp] = pi;
            s_sj[it * 16 + grp] = pj;
            bsum += pj;
        }
    }
    __syncthreads();
    if (lane == 0) atomicAdd(&s_blkSj, bsum);
    __syncthreads();
    if (tid == 0) g_part_Sj[bid] = s_blkSj;

    grid_barrier(epoch + 1);

    // ---------------- Sj reduce for my batch ---------------------------------
    if (tid == 0) s_Sj = 0.0f;
    __syncthreads();
    if (tid < 64) atomicAdd(&s_Sj, __ldcg(&g_part_Sj[bb * 64 + tid]));
    __syncthreads();
    const float Sj = s_Sj;

    // ---------------- Phase 2: u/v accumulation (RED into g_u/g_v) -----------
    float4 au = make_float4(0.f, 0.f, 0.f, 0.f);
    float4 av = make_float4(0.f, 0.f, 0.f, 0.f);
    #pragma unroll
    for (int it = 0; it < ITERS; ++it) {
        int lr = it * 16 + grp;
        float si = s_si[lr], sj = s_sj[lr];
        float d  = rsqrtf(fmaxf((float)Nn * (si + c) + Sj, 1.0f));
        float sd = sj * d;
        au.x += d  * xv[it].x;  au.y += d  * xv[it].y;
        au.z += d  * xv[it].z;  au.w += d  * xv[it].w;
        av.x += sd * xv[it].x;  av.y += sd * xv[it].y;
        av.z += sd * xv[it].z;  av.w += sd * xv[it].w;
    }
    s_pu[grp * Ff + lane * 4 + 0] = au.x;
    s_pu[grp * Ff + lane * 4 + 1] = au.y;
    s_pu[grp * Ff + lane * 4 + 2] = au.z;
    s_pu[grp * Ff + lane * 4 + 3] = au.w;
    s_pv[grp * Ff + lane * 4 + 0] = av.x;
    s_pv[grp * Ff + lane * 4 + 1] = av.y;
    s_pv[grp * Ff + lane * 4 + 2] = av.z;
    s_pv[grp * Ff + lane * 4 + 3] = av.w;
    __syncthreads();
    if (tid < 64) {
        float a = 0.f;
        #pragma unroll
        for (int g = 0; g < 16; ++g) a += s_pu[g * Ff + tid];
        atomicAdd(&g_u[bb * Ff + tid], a);
    } else if (tid < 128) {
        int f = tid - 64;
        float a = 0.f;
        #pragma unroll
        for (int g = 0; g < 16; ++g) a += s_pv[g * Ff + f];
        atomicAdd(&g_v[bb * Ff + f], a);
    }

    grid_barrier(epoch + 2);

    // ---------------- Phase 3: read u/v, micro-GEMM P/Q ----------------------
    if (tid < 64)        s_u[tid]      = __ldcg(&g_u[bb * Ff + tid]);
    else if (tid < 128)  s_v[tid - 64] = __ldcg(&g_v[bb * Ff + tid - 64]);
    __syncthreads();
    if (tid < 64) {
        float p = 0.f;
        #pragma unroll
        for (int f = 0; f < Ff; ++f) p = fmaf(s_u[f], s_W[f * Oo + tid], p);
        sP[tid] = p;
    } else if (tid < 128) {
        int o = tid - 64;
        float q = 0.f;
        #pragma unroll
        for (int f = 0; f < Ff; ++f) q = fmaf(s_v[f], s_W[f * Oo + o], q);
        sQ[o] = q;
    }
    __syncthreads();

    // ---------------- Phase 4: rank-1 epilogue --------------------------------
    const int o4 = lane * 4;
    const float P0 = sP[o4 + 0], P1 = sP[o4 + 1], P2 = sP[o4 + 2], P3 = sP[o4 + 3];
    const float Q0 = sQ[o4 + 0], Q1 = sQ[o4 + 1], Q2 = sQ[o4 + 2], Q3 = sQ[o4 + 3];
    const float B0 = sB[o4 + 0], B1 = sB[o4 + 1], B2 = sB[o4 + 2], B3 = sB[o4 + 3];
    #pragma unroll
    for (int it = 0; it < ITERS; ++it) {
        int lr = it * 16 + grp;
        float si = s_si[lr];
        float d  = rsqrtf(fmaxf((float)Nn * (si + c) + Sj, 1.0f));
        float a  = si + c;
        float4 r;
        r.x = fmaxf(fmaf(d, fmaf(a, P0, Q0), B0), 0.0f);
        r.y = fmaxf(fmaf(d, fmaf(a, P1, Q1), B1), 0.0f);
        r.z = fmaxf(fmaf(d, fmaf(a, P2, Q2), B2), 0.0f);
        r.w = fmaxf(fmaf(d, fmaf(a, P3, Q3), B3), 0.0f);
        reinterpret_cast<float4*>(out)[(row0 + lr) * 16 + lane] = r;
    }
}

extern "C" void kernel_launch(void* const* d_in, const int* in_sizes, int n_in,
                              void* d_out, int out_size) {
    const float* x      = (const float*)d_in[0];
    const float* adj_w  = (const float*)d_in[1];
    const float* adj_b  = (const float*)d_in[2];
    const float* weight = (const float*)d_in[3];
    const float* bias   = (const float*)d_in[4];
    float* out = (float*)d_out;

    k_fused<<<GRID, TPB>>>(x, adj_w, adj_b, weight, bias, out);
}

// round 4
// speedup vs baseline: 1.9599x; 1.9599x over previous
#include <cuda_runtime.h>

#define Bb 2
#define Nn 8192
#define Ff 64
#define Oo 64
#define GRID 128
#define GPB  64          // blocks per batch (barrier group size)
#define TPB 256
#define RPB 128          // rows per block
#define ITERS 8          // RPB / 16 row groups

// Scratch (__device__ globals; zero at module load, kept consistent per launch).
__device__ float g_part_Sj[GRID];
__device__ float g_u[Bb * Ff];               // atomic accumulators (zeroed in-kernel)
__device__ float g_v[Bb * Ff];
__device__ unsigned long long g_ctr2[Bb];    // monotone per-batch barrier counters

__device__ __forceinline__ unsigned long long ctr_load_acq(const unsigned long long* p) {
    unsigned long long v;
    asm volatile("ld.acquire.gpu.global.u64 %0, [%1];" : "=l"(v) : "l"(p) : "memory");
    return v;
}

// Per-batch grid barrier: 64 participants, single poller per block, nanosleep
// backoff. Counter is monotone (never reset): each launch adds 2*GPB per batch,
// epoch E = token / (2*GPB) recovers this launch's targets.
__device__ __forceinline__ void batch_barrier(int bb, unsigned int phase) {
    __syncthreads();
    if (threadIdx.x == 0) {
        __threadfence();
        unsigned long long token = atomicAdd(&g_ctr2[bb], 1ULL);
        unsigned long long E = token / (2ULL * GPB);
        unsigned long long target = E * (2ULL * GPB) + (unsigned long long)phase * GPB;
        while (ctr_load_acq(&g_ctr2[bb]) < target) __nanosleep(20);
    }
    __syncthreads();
}

__global__ void __launch_bounds__(TPB, 1) k_fused(
    const float* __restrict__ x, const float* __restrict__ adj_w,
    const float* __restrict__ adj_b, const float* __restrict__ weight,
    const float* __restrict__ bias, float* __restrict__ out)
{
    __shared__ float s_si[RPB], s_sj[RPB];
    __shared__ float s_pu[16 * Ff];
    __shared__ float s_pv[16 * Ff];
    __shared__ float s_u[Ff], s_v[Ff];
    __shared__ float sP[Oo], sQ[Oo], sB[Oo];
    __shared__ float s_W[Ff * Oo];            // 16 KB weight stage
    __shared__ float s_blkSj, s_Sj;

    const int tid  = threadIdx.x;
    const int lane = tid & 15;                // feature quad
    const int grp  = tid >> 4;                // row group
    const int bid  = blockIdx.x;
    const int bb   = bid >> 6;                // batch (64 blocks/batch)
    const int row0 = bid * RPB;

    const float c = adj_b[0];
    if (tid == 0) s_blkSj = 0.0f;

    // Stage weight + bias into shared (hidden under the phase-1 DRAM load).
    #pragma unroll
    for (int k = 0; k < Ff * Oo / TPB; ++k)
        s_W[k * TPB + tid] = weight[k * TPB + tid];
    if (tid < Oo) sB[tid] = bias[tid];

    // One block per batch zeroes that batch's u/v accumulators BEFORE barrier 1;
    // the barrier's release/acquire publishes the zeros before any atomics land.
    if ((bid & 63) == 0 && tid < Ff) {
        g_u[bb * Ff + tid] = 0.0f;
        g_v[bb * Ff + tid] = 0.0f;
    }

    // ---------------- Phase 1: si/sj + block Sj partial ----------------------
    // x rows live in registers for the whole kernel: read from DRAM exactly once.
    float4 xv[ITERS];
    #pragma unroll
    for (int it = 0; it < ITERS; ++it)
        xv[it] = reinterpret_cast<const float4*>(x)[(row0 + it * 16 + grp) * 16 + lane];

    const float4 wj = reinterpret_cast<const float4*>(adj_w)[lane];
    const float4 wi = reinterpret_cast<const float4*>(adj_w)[16 + lane];

    float bsum = 0.0f;
    #pragma unroll
    for (int it = 0; it < ITERS; ++it) {
        float pj = xv[it].x * wj.x + xv[it].y * wj.y + xv[it].z * wj.z + xv[it].w * wj.w;
        float pi = xv[it].x * wi.x + xv[it].y * wi.y + xv[it].z * wi.z + xv[it].w * wi.w;
        #pragma unroll
        for (int off = 8; off; off >>= 1) {
            pj += __shfl_down_sync(0xffffffffu, pj, off, 16);
            pi += __shfl_down_sync(0xffffffffu, pi, off, 16);
        }
        if (lane == 0) {
            s_si[it * 16 + grp] = pi;
            s_sj[it * 16 + grp] = pj;
            bsum += pj;
        }
    }
    __syncthreads();
    if (lane == 0) atomicAdd(&s_blkSj, bsum);
    __syncthreads();
    if (tid == 0) g_part_Sj[bid] = s_blkSj;

    batch_barrier(bb, 1);

    // ---------------- Sj reduce for my batch ---------------------------------
    if (tid == 0) s_Sj = 0.0f;
    __syncthreads();
    if (tid < GPB) atomicAdd(&s_Sj, __ldcg(&g_part_Sj[bb * GPB + tid]));
    __syncthreads();
    const float Sj = s_Sj;

    // ---------------- Phase 2: u/v accumulation (RED into g_u/g_v) -----------
    float4 au = make_float4(0.f, 0.f, 0.f, 0.f);
    float4 av = make_float4(0.f, 0.f, 0.f, 0.f);
    #pragma unroll
    for (int it = 0; it < ITERS; ++it) {
        int lr = it * 16 + grp;
        float si = s_si[lr], sj = s_sj[lr];
        float d  = rsqrtf(fmaxf((float)Nn * (si + c) + Sj, 1.0f));
        float sd = sj * d;
        au.x += d  * xv[it].x;  au.y += d  * xv[it].y;
        au.z += d  * xv[it].z;  au.w += d  * xv[it].w;
        av.x += sd * xv[it].x;  av.y += sd * xv[it].y;
        av.z += sd * xv[it].z;  av.w += sd * xv[it].w;
    }
    s_pu[grp * Ff + lane * 4 + 0] = au.x;
    s_pu[grp * Ff + lane * 4 + 1] = au.y;
    s_pu[grp * Ff + lane * 4 + 2] = au.z;
    s_pu[grp * Ff + lane * 4 + 3] = au.w;
    s_pv[grp * Ff + lane * 4 + 0] = av.x;
    s_pv[grp * Ff + lane * 4 + 1] = av.y;
    s_pv[grp * Ff + lane * 4 + 2] = av.z;
    s_pv[grp * Ff + lane * 4 + 3] = av.w;
    __syncthreads();
    if (tid < 64) {
        float a = 0.f;
        #pragma unroll
        for (int g = 0; g < 16; ++g) a += s_pu[g * Ff + tid];
        atomicAdd(&g_u[bb * Ff + tid], a);          // fire-and-forget RED
    } else if (tid < 128) {
        int f = tid - 64;
        float a = 0.f;
        #pragma unroll
        for (int g = 0; g < 16; ++g) a += s_pv[g * Ff + f];
        atomicAdd(&g_v[bb * Ff + f], a);
    }

    batch_barrier(bb, 2);

    // ---------------- Phase 3: read u/v, micro-GEMM P/Q ----------------------
    if (tid < 64)        s_u[tid]      = __ldcg(&g_u[bb * Ff + tid]);
    else if (tid < 128)  s_v[tid - 64] = __ldcg(&g_v[bb * Ff + tid - 64]);
    __syncthreads();
    if (tid < 64) {
        float p = 0.f;
        #pragma unroll
        for (int f = 0; f < Ff; ++f) p = fmaf(s_u[f], s_W[f * Oo + tid], p);
        sP[tid] = p;
    } else if (tid < 128) {
        int o = tid - 64;
        float q = 0.f;
        #pragma unroll
        for (int f = 0; f < Ff; ++f) q = fmaf(s_v[f], s_W[f * Oo + o], q);
        sQ[o] = q;
    }
    __syncthreads();

    // ---------------- Phase 4: rank-1 epilogue --------------------------------
    const int o4 = lane * 4;
    const float P0 = sP[o4 + 0], P1 = sP[o4 + 1], P2 = sP[o4 + 2], P3 = sP[o4 + 3];
    const float Q0 = sQ[o4 + 0], Q1 = sQ[o4 + 1], Q2 = sQ[o4 + 2], Q3 = sQ[o4 + 3];
    const float B0 = sB[o4 + 0], B1 = sB[o4 + 1], B2 = sB[o4 + 2], B3 = sB[o4 + 3];
    #pragma unroll
    for (int it = 0; it < ITERS; ++it) {
        int lr = it * 16 + grp;
        float si = s_si[lr];
        float d  = rsqrtf(fmaxf((float)Nn * (si + c) + Sj, 1.0f));
        float a  = si + c;
        float4 r;
        r.x = fmaxf(fmaf(d, fmaf(a, P0, Q0), B0), 0.0f);
        r.y = fmaxf(fmaf(d, fmaf(a, P1, Q1), B1), 0.0f);
        r.z = fmaxf(fmaf(d, fmaf(a, P2, Q2), B2), 0.0f);
        r.w = fmaxf(fmaf(d, fmaf(a, P3, Q3), B3), 0.0f);
        reinterpret_cast<float4*>(out)[(row0 + lr) * 16 + lane] = r;
    }
}

extern "C" void kernel_launch(void* const* d_in, const int* in_sizes, int n_in,
                              void* d_out, int out_size) {
    const float* x      = (const float*)d_in[0];
    const float* adj_w  = (const float*)d_in[1];
    const float* adj_b  = (const float*)d_in[2];
    const float* weight = (const float*)d_in[3];
    const float* bias   = (const float*)d_in[4];
    float* out = (float*)d_out;

    k_fused<<<GRID, TPB>>>(x, adj_w, adj_b, weight, bias, out);
}